// round 2
// baseline (speedup 1.0000x reference)
#include <cuda_runtime.h>

typedef unsigned long long ull;

// ---------------- packed f32x2 helpers (Blackwell FFMA2 path) ----------------
__device__ __forceinline__ ull pack2(float a, float b) {
    ull r; asm("mov.b64 %0, {%1,%2};" : "=l"(r) : "f"(a), "f"(b)); return r;
}
__device__ __forceinline__ float2 unpack2(ull v) {
    float2 f; asm("mov.b64 {%0,%1}, %2;" : "=f"(f.x), "=f"(f.y) : "l"(v)); return f;
}
__device__ __forceinline__ ull ffma2(ull a, ull b, ull c) {
    ull d; asm("fma.rn.f32x2 %0, %1, %2, %3;" : "=l"(d) : "l"(a), "l"(b), "l"(c)); return d;
}
__device__ __forceinline__ ull fadd2(ull a, ull b) {
    ull d; asm("add.rn.f32x2 %0, %1, %2;" : "=l"(d) : "l"(a), "l"(b)); return d;
}

// HW tanh (sm_75+): single MUFU, lat~16, abs err ~6e-4
__device__ __forceinline__ float tanh_fast(float x) {
    float y; asm("tanh.approx.f32 %0, %1;" : "=f"(y) : "f"(x)); return y;
}
__device__ __forceinline__ float sig_fast(float x) {
    return fmaf(0.5f, tanh_fast(0.5f * x), 0.5f);
}
// accurate sigmoid for the final output head
__device__ __forceinline__ float sigmoidf_acc(float x) {
    return __fdividef(1.f, 1.f + __expf(-x));
}

#define B_  256
#define S_  1024
#define F_  64
#define H_  64
#define G_  256   // 4*H

// Column pairing: pair index p owns gate columns (c0, c1):
//   p <  64 : (p,      p+64 )  = (i_p, f_p)
//   p >= 64 : (p+64,   p+128)  = (c_{p-64}, o_{p-64})
// xz scratch stored in this packed layout: [t][b][p] as float2. 268MB.
__device__ ull g_xz[(size_t)S_ * B_ * 128];

// =====================================================================
// Kernel A: xz = x @ kernel + bias   (input-projection GEMM, FFMA2)
// Grid: 1024 CTAs x 256 thr. Each CTA: 64 iterations x 4 (b,t)-rows.
// =====================================================================
__global__ void __launch_bounds__(256, 1) lstm_xgemm(
    const float* __restrict__ x, const float* __restrict__ kern,
    const float* __restrict__ bias)
{
    const int tid  = threadIdx.x;
    const int j    = tid & 127;
    const int half = tid >> 7;
    const int c0   = (j < 64) ? j : j + 64;
    const int c1   = c0 + 64;

    // Kernel columns (c0, c1) packed, in registers: 64 x 64-bit
    ull wk[64];
#pragma unroll
    for (int k = 0; k < 64; k++)
        wk[k] = pack2(kern[k * G_ + c0], kern[k * G_ + c1]);
    const ull bj = pack2(bias[c0], bias[c1]);

    __shared__ __align__(16) ull xdup[2][4][64];   // x values duplicated into both lanes

    const int lr = tid >> 6;   // 0..3 : which row this thread loads
    const int lk = tid & 63;   // which feature
    const int qbase = blockIdx.x * 64;             // 64 quads (of 4 rows) per CTA

    float v = x[(size_t)(qbase * 4 + lr) * F_ + lk];   // prefetch iter 0
    int buf = 0;
    for (int i = 0; i < 64; i++) {
        xdup[buf][lr][lk] = pack2(v, v);
        __syncthreads();
        if (i + 1 < 64)
            v = x[(size_t)((qbase + i + 1) * 4 + lr) * F_ + lk];  // prefetch next

        const ull* xa = xdup[buf][half];       // row n0
        const ull* xb = xdup[buf][half + 2];   // row n0+2
        ull a0 = bj, a1 = 0ull, a2 = bj, a3 = 0ull;
#pragma unroll
        for (int k = 0; k < 64; k += 2) {
            const ulonglong2 va = *(const ulonglong2*)(xa + k);  // LDS.128
            const ulonglong2 vb = *(const ulonglong2*)(xb + k);
            a0 = ffma2(wk[k],     va.x, a0);
            a1 = ffma2(wk[k + 1], va.y, a1);
            a2 = ffma2(wk[k],     vb.x, a2);
            a3 = ffma2(wk[k + 1], vb.y, a3);
        }
        const ull r0 = fadd2(a0, a1);
        const ull r1 = fadd2(a2, a3);

        const int n0 = (qbase + i) * 4 + half;   // global row index = b*S + t
        const int n1 = n0 + 2;
        {
            const int bb = n0 >> 10, tt = n0 & 1023;
            g_xz[((size_t)tt * B_ + bb) * 128 + j] = r0;
        }
        {
            const int bb = n1 >> 10, tt = n1 & 1023;
            g_xz[((size_t)tt * B_ + bb) * 128 + j] = r1;
        }
        buf ^= 1;
    }
}

// =====================================================================
// Kernel B: sequential LSTM recurrence + fused dense head.
// Grid: 256 CTAs x 128 thr — ONE batch row per CTA, ~2 CTAs/SM so
// independent CTAs hide each other's barrier/latency stalls.
//   thread j owns pair (c0,c1): j<64 -> (z_i[j], z_f[j])
//                               j>=64 -> (z_c[j-64], z_o[j-64])
// Phase 1 (all): matvec + OWN activations -> j>=64 publish (tanh(zc), sig(zo))
// Phase 2: j<64 do c/h update (short chain); warp 2 computes dense head
//          for step t-1 (double-buffered h makes it race-free).
// =====================================================================
__global__ void __launch_bounds__(128, 2) lstm_recur(
    const float* __restrict__ rec, const float* __restrict__ dw,
    const float* __restrict__ db, float* __restrict__ out)
{
    const int j    = threadIdx.x;        // 0..127
    const int brow = blockIdx.x;
    const int c0   = (j < 64) ? j : j + 64;
    const int c1   = c0 + 64;

    // Recurrent weight column pair, packed, in registers
    ull wr[64];
#pragma unroll
    for (int k = 0; k < 64; k++)
        wr[k] = pack2(rec[k * G_ + c0], rec[k * G_ + c1]);

    __shared__ __align__(16) ull hdup[2][64];   // [parity][k], h duplicated in both lanes
    __shared__ float2 abuf[64];                 // (tanh(zc), sig(zo)) from threads j>=64

    if (j < 64) hdup[1][j] = 0ull;              // h(-1) = 0 at parity 1

    const int  wid    = j >> 5;
    const int  lane   = j & 31;
    const bool isGate = (j < 64);
    const bool isOut  = (wid == 2);

    float c = 0.f;
    const float dwa   = dw[lane];
    const float dwb   = dw[lane + 32];
    const float dbias = db[0];

    const ull*   zp = g_xz + (size_t)brow * 128 + j;
    const size_t ZS = (size_t)B_ * 128;

    ull z0 = zp[0];        // depth-2 z prefetch pipeline
    ull z1 = zp[ZS];
    __syncthreads();

    for (int t = 0; t < S_; t++) {
        ull acc0 = z0;                       // z-input (loaded 2 steps ago)
        z0 = z1;
        if (t + 2 < S_) z1 = zp[(size_t)(t + 2) * ZS];

        const int  pr = (t & 1) ^ 1;         // parity holding h(t-1)
        const ull* hp = hdup[pr];
        ull acc1 = 0ull, acc2 = 0ull, acc3 = 0ull;
#pragma unroll
        for (int k = 0; k < 64; k += 4) {
            const ulonglong2 h0 = *(const ulonglong2*)(hp + k);      // LDS.128
            const ulonglong2 h1 = *(const ulonglong2*)(hp + k + 2);
            acc0 = ffma2(wr[k],     h0.x, acc0);
            acc1 = ffma2(wr[k + 1], h0.y, acc1);
            acc2 = ffma2(wr[k + 2], h1.x, acc2);
            acc3 = ffma2(wr[k + 3], h1.y, acc3);
        }
        const float2 zv = unpack2(fadd2(fadd2(acc0, acc1), fadd2(acc2, acc3)));

        // own activations BEFORE the barrier (warp-uniform branch)
        float g0, g1;
        if (isGate) {                        // (z_i, z_f) -> (ig, fg)
            g0 = sig_fast(zv.x);
            g1 = sig_fast(zv.y);
        } else {                             // (z_c, z_o) -> (tanh, og)
            g0 = tanh_fast(zv.x);
            g1 = sig_fast(zv.y);
            abuf[j - 64] = make_float2(g0, g1);
        }
        __syncthreads();

        if (isGate) {
            const float2 p = abuf[j];        // (tanh(zc), og)
            c = fmaf(g1, c, g0 * p.x);
            const float h = p.y * tanh_fast(c);
            hdup[t & 1][j] = pack2(h, h);    // publish h(t) to parity t&1
        } else if (isOut && t > 0) {
            // out(t-1) from h(t-1) at parity pr — disjoint from gate writes
            const ull* hh = hdup[pr];
            float p = unpack2(hh[lane]).x * dwa + unpack2(hh[lane + 32]).x * dwb;
#pragma unroll
            for (int off = 16; off; off >>= 1)
                p += __shfl_xor_sync(0xffffffffu, p, off);
            if (lane == 0)
                out[(size_t)brow * S_ + (t - 1)] = sigmoidf_acc(p + dbias);
        }
        __syncthreads();
    }

    // Final output: h(S-1) lives at parity (S-1)&1 = 1
    if (isOut) {
        const ull* hh = hdup[1];
        float p = unpack2(hh[lane]).x * dwa + unpack2(hh[lane + 32]).x * dwb;
#pragma unroll
        for (int off = 16; off; off >>= 1)
            p += __shfl_xor_sync(0xffffffffu, p, off);
        if (lane == 0)
            out[(size_t)brow * S_ + (S_ - 1)] = sigmoidf_acc(p + dbias);
    }
}

// =====================================================================
extern "C" void kernel_launch(void* const* d_in, const int* in_sizes, int n_in,
                              void* d_out, int out_size)
{
    const float* x    = (const float*)d_in[0];  // [256,1024,64]
    const float* kern = (const float*)d_in[1];  // [64,256]
    const float* rec  = (const float*)d_in[2];  // [64,256]
    const float* bias = (const float*)d_in[3];  // [256]
    const float* dw   = (const float*)d_in[4];  // [64,1]
    const float* db   = (const float*)d_in[5];  // [1]
    float* out = (float*)d_out;                 // [256,1024,1]

    lstm_xgemm<<<1024, 256>>>(x, kern, bias);
    lstm_recur<<<256, 128>>>(rec, dw, db, out);
}

// round 3
// speedup vs baseline: 1.0566x; 1.0566x over previous
#include <cuda_runtime.h>

typedef unsigned long long ull;

// ---------------- packed f32x2 helpers (Blackwell FFMA2 path) ----------------
__device__ __forceinline__ ull pack2(float a, float b) {
    ull r; asm("mov.b64 %0, {%1,%2};" : "=l"(r) : "f"(a), "f"(b)); return r;
}
__device__ __forceinline__ float2 unpack2(ull v) {
    float2 f; asm("mov.b64 {%0,%1}, %2;" : "=f"(f.x), "=f"(f.y) : "l"(v)); return f;
}
__device__ __forceinline__ ull ffma2(ull a, ull b, ull c) {
    ull d; asm("fma.rn.f32x2 %0, %1, %2, %3;" : "=l"(d) : "l"(a), "l"(b), "l"(c)); return d;
}
__device__ __forceinline__ ull fadd2(ull a, ull b) {
    ull d; asm("add.rn.f32x2 %0, %1, %2;" : "=l"(d) : "l"(a), "l"(b)); return d;
}

// HW tanh (single MUFU op); validated in round 2 at rel_err ~7e-7 end-to-end
__device__ __forceinline__ float tanh_fast(float x) {
    float y; asm("tanh.approx.f32 %0, %1;" : "=f"(y) : "f"(x)); return y;
}
__device__ __forceinline__ float sig_fast(float x) {
    return fmaf(0.5f, tanh_fast(0.5f * x), 0.5f);
}
__device__ __forceinline__ float sigmoidf_acc(float x) {
    return __fdividef(1.f, 1.f + __expf(-x));
}

#define B_  256
#define S_  1024
#define F_  64
#define H_  64
#define G_  256   // 4*H

// Column pairing (round-1 layout): pair j -> gate columns (j, j+128):
//   j <  64 : (z_i[j],    z_c[j])
//   j >= 64 : (z_f[j-64], z_o[j-64])
// xz scratch: [t][b][j] packed float2. 268MB.
__device__ ull g_xz[(size_t)S_ * B_ * 128];

// =====================================================================
// Kernel A: xz = x @ kernel + bias  (round-1 version, verbatim: 292us)
// Grid: 1024 CTAs x 256 thr. Each CTA: 64 iterations x 4 (b,t)-rows.
// =====================================================================
__global__ void __launch_bounds__(256, 1) lstm_xgemm(
    const float* __restrict__ x, const float* __restrict__ kern,
    const float* __restrict__ bias)
{
    const int tid  = threadIdx.x;
    const int j    = tid & 127;
    const int half = tid >> 7;

    ull wk[64];
#pragma unroll
    for (int k = 0; k < 64; k++)
        wk[k] = pack2(kern[k * G_ + j], kern[k * G_ + 128 + j]);
    const ull bj = pack2(bias[j], bias[j + 128]);

    __shared__ __align__(16) ull xdup[2][4][64];

    const int lr = tid >> 6;
    const int lk = tid & 63;
    const int qbase = blockIdx.x * 64;

    float v = x[(size_t)(qbase * 4 + lr) * F_ + lk];
    int buf = 0;
    for (int i = 0; i < 64; i++) {
        xdup[buf][lr][lk] = pack2(v, v);
        __syncthreads();
        if (i + 1 < 64)
            v = x[(size_t)((qbase + i + 1) * 4 + lr) * F_ + lk];

        const ull* xa = xdup[buf][half];
        const ull* xb = xdup[buf][half + 2];
        ull a0 = bj, a0b = 0ull, a1 = bj, a1b = 0ull;
#pragma unroll
        for (int k = 0; k < 64; k += 2) {
            a0  = ffma2(wk[k],     xa[k],     a0);
            a0b = ffma2(wk[k + 1], xa[k + 1], a0b);
            a1  = ffma2(wk[k],     xb[k],     a1);
            a1b = ffma2(wk[k + 1], xb[k + 1], a1b);
        }
        const ull r0 = fadd2(a0, a0b);
        const ull r1 = fadd2(a1, a1b);

        const int n0 = (qbase + i) * 4 + half;
        const int n1 = n0 + 2;
        {
            const int bb = n0 >> 10, tt = n0 & 1023;
            g_xz[((size_t)tt * B_ + bb) * 128 + j] = r0;
        }
        {
            const int bb = n1 >> 10, tt = n1 & 1023;
            g_xz[((size_t)tt * B_ + bb) * 128 + j] = r1;
        }
        buf ^= 1;
    }
}

// =====================================================================
// Kernel B: LSTM recurrence, SPLIT-K so 2 CTAs co-reside per SM.
// Grid: 256 CTAs x 256 thr — ONE batch row per CTA.
//   tid = kh*128 + j : kh = K-half (0/1), j = gate-column pair.
//   Each thread holds 32 packed weights (64 regs) -> ~110 regs total,
//   so __launch_bounds__(256,2) gives 16 warps/SM to hide latency.
// Per step:
//   A: all threads: partial matvec over own K-half; kh=1 -> pbuf. BAR1
//   B: kh=0: z = xz + own + pbuf; own activations; j>=64 publish
//      (sig(zf), sig(zo)) to abuf.                              BAR2
//   C: kh=0,j<64: c,h update -> hdup[t&1]; warp 4: dense head
//      for step t-1 (reads hdup[pr], disjoint from writes).     BAR3
// =====================================================================
__global__ void __launch_bounds__(256, 2) lstm_recur(
    const float* __restrict__ rec, const float* __restrict__ dw,
    const float* __restrict__ db, float* __restrict__ out)
{
    const int tid  = threadIdx.x;
    const int j    = tid & 127;
    const int kh   = tid >> 7;          // K-half: 0 or 1
    const int kb   = kh << 5;           // K base: 0 or 32
    const int brow = blockIdx.x;

    // 32 packed recurrent-weight rows for own K-half, columns (j, j+128)
    ull wr[32];
#pragma unroll
    for (int k = 0; k < 32; k++)
        wr[k] = pack2(rec[(kb + k) * G_ + j], rec[(kb + k) * G_ + 128 + j]);

    __shared__ __align__(16) ull    hdup[2][64];  // [parity][k], h dup in both lanes
    __shared__ __align__(16) ull    pbuf[128];    // kh=1 partial sums per pair
    __shared__ __align__(16) float2 abuf[64];     // (sig(zf), sig(zo)) per gate idx

    if (tid < 64) hdup[1][tid] = 0ull;            // h(-1)=0 at parity 1

    const int  wid  = tid >> 5;
    const int  lane = tid & 31;

    float c = 0.f;
    const float dwa   = dw[lane];
    const float dwb   = dw[lane + 32];
    const float dbias = db[0];

    // xz stream: only kh=0 threads consume it (pair j of own row)
    const ull*   zp = g_xz + (size_t)brow * 128 + j;
    const size_t ZS = (size_t)B_ * 128;
    ull z0 = 0ull, z1 = 0ull;
    if (kh == 0) { z0 = zp[0]; z1 = zp[ZS]; }
    __syncthreads();

    float a_ic = 0.f;   // i*tanh(zc), carried A->C in registers (j<64, kh=0)

    for (int t = 0; t < S_; t++) {
        const int  pr = (t & 1) ^ 1;              // parity of h(t-1)
        const ull* hp = hdup[pr] + kb;

        // ---- phase A: partial matvec over own K-half ----
        ull acc0 = 0ull, acc1 = 0ull, acc2 = 0ull, acc3 = 0ull;
#pragma unroll
        for (int k = 0; k < 32; k += 4) {
            acc0 = ffma2(wr[k],     hp[k],     acc0);
            acc1 = ffma2(wr[k + 1], hp[k + 1], acc1);
            acc2 = ffma2(wr[k + 2], hp[k + 2], acc2);
            acc3 = ffma2(wr[k + 3], hp[k + 3], acc3);
        }
        const ull part = fadd2(fadd2(acc0, acc1), fadd2(acc2, acc3));
        if (kh == 1) pbuf[j] = part;
        __syncthreads();                          // BAR1

        // ---- phase B: combine + own activations (kh=0 only) ----
        if (kh == 0) {
            const ull zfull = fadd2(fadd2(z0, part), pbuf[j]);
            z0 = z1;
            if (t + 2 < S_) z1 = zp[(size_t)(t + 2) * ZS];
            const float2 zv = unpack2(zfull);
            if (j < 64) {                         // (z_i, z_c)
                a_ic = sig_fast(zv.x) * tanh_fast(zv.y);
            } else {                              // (z_f, z_o)
                abuf[j - 64] = make_float2(sig_fast(zv.x), sig_fast(zv.y));
            }
        }
        __syncthreads();                          // BAR2

        // ---- phase C: state update + overlapped dense head ----
        if (kh == 0 && j < 64) {
            const float2 fo = abuf[j];            // (fg, og)
            c = fmaf(fo.x, c, a_ic);
            const float h = fo.y * tanh_fast(c);
            hdup[t & 1][j] = pack2(h, h);
        } else if (wid == 4 && t > 0) {
            const ull* hh = hdup[pr];
            float p = unpack2(hh[lane]).x * dwa + unpack2(hh[lane + 32]).x * dwb;
#pragma unroll
            for (int off = 16; off; off >>= 1)
                p += __shfl_xor_sync(0xffffffffu, p, off);
            if (lane == 0)
                out[(size_t)brow * S_ + (t - 1)] = sigmoidf_acc(p + dbias);
        }
        __syncthreads();                          // BAR3
    }

    // final output: h(S-1) at parity 1
    if (wid == 4) {
        const ull* hh = hdup[1];
        float p = unpack2(hh[lane]).x * dwa + unpack2(hh[lane + 32]).x * dwb;
#pragma unroll
        for (int off = 16; off; off >>= 1)
            p += __shfl_xor_sync(0xffffffffu, p, off);
        if (lane == 0)
            out[(size_t)brow * S_ + (S_ - 1)] = sigmoidf_acc(p + dbias);
    }
}

// =====================================================================
extern "C" void kernel_launch(void* const* d_in, const int* in_sizes, int n_in,
                              void* d_out, int out_size)
{
    const float* x    = (const float*)d_in[0];  // [256,1024,64]
    const float* kern = (const float*)d_in[1];  // [64,256]
    const float* rec  = (const float*)d_in[2];  // [64,256]
    const float* bias = (const float*)d_in[3];  // [256]
    const float* dw   = (const float*)d_in[4];  // [64,1]
    const float* db   = (const float*)d_in[5];  // [1]
    float* out = (float*)d_out;                 // [256,1024,1]

    lstm_xgemm<<<1024, 256>>>(x, kern, bias);
    lstm_recur<<<256, 256>>>(rec, dw, db, out);
}

// round 4
// speedup vs baseline: 1.4966x; 1.4164x over previous
#include <cuda_runtime.h>

typedef unsigned long long ull;

// ---------------- packed f32x2 helpers (Blackwell FFMA2 path) ----------------
__device__ __forceinline__ ull pack2(float a, float b) {
    ull r; asm("mov.b64 %0, {%1,%2};" : "=l"(r) : "f"(a), "f"(b)); return r;
}
__device__ __forceinline__ float2 unpack2(ull v) {
    float2 f; asm("mov.b64 {%0,%1}, %2;" : "=f"(f.x), "=f"(f.y) : "l"(v)); return f;
}
__device__ __forceinline__ ull ffma2(ull a, ull b, ull c) {
    ull d; asm("fma.rn.f32x2 %0, %1, %2, %3;" : "=l"(d) : "l"(a), "l"(b), "l"(c)); return d;
}
__device__ __forceinline__ ull fadd2(ull a, ull b) {
    ull d; asm("add.rn.f32x2 %0, %1, %2;" : "=l"(d) : "l"(a), "l"(b)); return d;
}

// HW tanh (single MUFU op); validated rel_err ~7e-7 end-to-end
__device__ __forceinline__ float tanh_fast(float x) {
    float y; asm("tanh.approx.f32 %0, %1;" : "=f"(y) : "f"(x)); return y;
}
__device__ __forceinline__ float sig_fast(float x) {
    return fmaf(0.5f, tanh_fast(0.5f * x), 0.5f);
}
__device__ __forceinline__ float sigmoidf_acc(float x) {
    return __fdividef(1.f, 1.f + __expf(-x));
}

#define B_  256
#define S_  1024
#define F_  64
#define H_  64
#define G_  256   // 4*H

// Pair mapping: thread/pair index p -> u = p>>1, s = p&1
//   s=0: columns (u,     u+64 ) = (z_i[u],  z_f[u])
//   s=1: columns (u+128, u+192) = (z_c[u],  z_o[u])
// xz scratch: [t][b][p] packed float2 (col c0, col c1). 268MB.
__device__ ull g_xz[(size_t)S_ * B_ * 128];

// =====================================================================
// Kernel A: xz = x @ kernel + bias   (k-packed x: 64 LDS/iter/thread)
// Grid: 1024 CTAs x 256 thr. Each CTA: 64 iterations x 4 (b,t)-rows.
// =====================================================================
__global__ void __launch_bounds__(256, 1) lstm_xgemm(
    const float* __restrict__ x, const float* __restrict__ kern,
    const float* __restrict__ bias)
{
    const int tid  = threadIdx.x;
    const int j    = tid & 127;
    const int half = tid >> 7;
    const int u    = j >> 1;
    const int s    = j & 1;
    const int c0   = u + (s ? 128 : 0);
    const int c1   = c0 + 64;

    // weights packed along k: wX[m] = (kern[2m][c], kern[2m+1][c])
    ull wA[32], wB[32];
#pragma unroll
    for (int m = 0; m < 32; m++) {
        wA[m] = pack2(kern[(2 * m) * G_ + c0], kern[(2 * m + 1) * G_ + c0]);
        wB[m] = pack2(kern[(2 * m) * G_ + c1], kern[(2 * m + 1) * G_ + c1]);
    }
    const float bc0 = bias[c0], bc1 = bias[c1];

    __shared__ __align__(16) ull xpk[2][4][32];   // x packed (x_2m, x_2m+1) per row

    // loader threads: tid<128 -> row lr, k-pair lm
    const int lr = (tid >> 5) & 3;
    const int lm = tid & 31;
    const int qbase = blockIdx.x * 64;

    float2 v = make_float2(0.f, 0.f);
    if (tid < 128)
        v = *(const float2*)(x + (size_t)(qbase * 4 + lr) * F_ + 2 * lm);

    int buf = 0;
    for (int i = 0; i < 64; i++) {
        if (tid < 128) xpk[buf][lr][lm] = pack2(v.x, v.y);
        __syncthreads();
        if (tid < 128 && i + 1 < 64)
            v = *(const float2*)(x + (size_t)((qbase + i + 1) * 4 + lr) * F_ + 2 * lm);

        const ull* xa = xpk[buf][half];       // row n0
        const ull* xb = xpk[buf][half + 2];   // row n0+2
        ull a0 = 0, a1 = 0, a2 = 0, a3 = 0;   // row A, cols c0/c1
        ull b0 = 0, b1 = 0, b2 = 0, b3 = 0;   // row B
#pragma unroll
        for (int m = 0; m < 32; m += 2) {
            const ull xa0 = xa[m], xa1 = xa[m + 1];
            const ull xb0 = xb[m], xb1 = xb[m + 1];
            a0 = ffma2(wA[m],     xa0, a0);
            a1 = ffma2(wA[m + 1], xa1, a1);
            a2 = ffma2(wB[m],     xa0, a2);
            a3 = ffma2(wB[m + 1], xa1, a3);
            b0 = ffma2(wA[m],     xb0, b0);
            b1 = ffma2(wA[m + 1], xb1, b1);
            b2 = ffma2(wB[m],     xb0, b2);
            b3 = ffma2(wB[m + 1], xb1, b3);
        }
        const float2 sa0 = unpack2(fadd2(a0, a1));
        const float2 sa1 = unpack2(fadd2(a2, a3));
        const float2 sb0 = unpack2(fadd2(b0, b1));
        const float2 sb1 = unpack2(fadd2(b2, b3));
        const ull r0 = pack2(bc0 + sa0.x + sa0.y, bc1 + sa1.x + sa1.y);
        const ull r1 = pack2(bc0 + sb0.x + sb0.y, bc1 + sb1.x + sb1.y);

        const int n0 = (qbase + i) * 4 + half;   // global row = b*S + t
        const int n1 = n0 + 2;
        {
            const int bb = n0 >> 10, tt = n0 & 1023;
            g_xz[((size_t)tt * B_ + bb) * 128 + j] = r0;
        }
        {
            const int bb = n1 >> 10, tt = n1 & 1023;
            g_xz[((size_t)tt * B_ + bb) * 128 + j] = r1;
        }
        buf ^= 1;
    }
}

// =====================================================================
// Kernel B: LSTM recurrence — ONE barrier per step, in-warp gate exchange.
// Grid: 256 CTAs x 128 thr, 1 batch row per CTA, 2 CTAs co-resident/SM.
//   thread p: u = p>>1 (hidden unit), s = p&1.
//     s=0 computes (z_i[u], z_f[u]); s=1 computes (z_c[u], z_o[u]).
//   Gate exchange via shfl_xor(1) within the warp; even lane does the
//   cell update and stores h_u (32-bit STS). Warp 3 computes the dense
//   head for step t-1 before its matvec (reads stable parity buffer).
// =====================================================================
__global__ void __launch_bounds__(128, 2) lstm_recur(
    const float* __restrict__ rec, const float* __restrict__ dw,
    const float* __restrict__ db, float* __restrict__ out)
{
    const int p    = threadIdx.x;     // 0..127
    const int u    = p >> 1;
    const int s    = p & 1;
    const int lane = p & 31;
    const int brow = blockIdx.x;
    const int c0   = u + (s ? 128 : 0);
    const int c1   = c0 + 64;

    // recurrent weights packed along k, per own two columns
    ull wA[32], wB[32];
#pragma unroll
    for (int m = 0; m < 32; m++) {
        wA[m] = pack2(rec[(2 * m) * G_ + c0], rec[(2 * m + 1) * G_ + c0]);
        wB[m] = pack2(rec[(2 * m) * G_ + c1], rec[(2 * m + 1) * G_ + c1]);
    }

    __shared__ __align__(16) ull hpk[2][32];   // [parity][m] = (h_2m, h_2m+1)

    if (p < 32) hpk[1][p] = 0ull;              // h(-1) = 0 at parity 1

    const bool isDense = (p >> 5) == 3;
    const float dwa   = dw[2 * lane];
    const float dwb   = dw[2 * lane + 1];
    const float dbias = db[0];

    float c = 0.f;
    const ull*   zp = g_xz + (size_t)brow * 128 + p;
    const size_t ZS = (size_t)B_ * 128;
    ull z0 = zp[0];                            // depth-2 z prefetch
    ull z1 = zp[ZS];
    __syncthreads();

    for (int t = 0; t < S_; t++) {
        const int  pr = (t & 1) ^ 1;           // parity holding h(t-1)
        const ull* hp = hpk[pr];

        // dense head for t-1, fully overlapped with other warps' matvec
        if (isDense && t > 0) {
            const float2 hh = unpack2(hp[lane]);
            float pd = hh.x * dwa + hh.y * dwb;
#pragma unroll
            for (int off = 16; off; off >>= 1)
                pd += __shfl_xor_sync(0xffffffffu, pd, off);
            if (lane == 0)
                out[(size_t)brow * S_ + (t - 1)] = sigmoidf_acc(pd + dbias);
        }

        // matvec: 32 LDS (broadcast), 64 FFMA2, 4 chains
        ull a0 = 0, a1 = 0, a2 = 0, a3 = 0;
#pragma unroll
        for (int m = 0; m < 32; m += 2) {
            const ull h0 = hp[m], h1 = hp[m + 1];
            a0 = ffma2(wA[m],     h0, a0);
            a1 = ffma2(wA[m + 1], h1, a1);
            a2 = ffma2(wB[m],     h0, a2);
            a3 = ffma2(wB[m + 1], h1, a3);
        }
        const float2 sa  = unpack2(fadd2(a0, a1));
        const float2 sb  = unpack2(fadd2(a2, a3));
        const float2 zin = unpack2(z0);
        z0 = z1;
        if (t + 2 < S_) z1 = zp[(size_t)(t + 2) * ZS];
        const float zv0 = zin.x + sa.x + sa.y;   // z_i (s=0) / z_c (s=1)
        const float zv1 = zin.y + sb.x + sb.y;   // z_f (s=0) / z_o (s=1)

        // own activations, then in-warp exchange with partner lane
        const float g0 = s ? tanh_fast(zv0) : sig_fast(zv0);
        const float g1 = sig_fast(zv1);
        const float t0 = __shfl_xor_sync(0xffffffffu, g0, 1);  // partner g0
        const float t1 = __shfl_xor_sync(0xffffffffu, g1, 1);  // partner g1

        if (s == 0) {                           // have (ig,fg)+(tc,og)
            c = fmaf(g1, c, g0 * t0);
            const float h = t1 * tanh_fast(c);
            ((float*)hpk[t & 1])[u] = h;        // publish h_u(t)
        }
        __syncthreads();                        // the ONLY barrier per step
    }

    // final output: h(S-1) at parity 1
    if (isDense) {
        const float2 hh = unpack2(hpk[1][lane]);
        float pd = hh.x * dwa + hh.y * dwb;
#pragma unroll
        for (int off = 16; off; off >>= 1)
            pd += __shfl_xor_sync(0xffffffffu, pd, off);
        if (lane == 0)
            out[(size_t)brow * S_ + (S_ - 1)] = sigmoidf_acc(pd + dbias);
    }
}

// =====================================================================
extern "C" void kernel_launch(void* const* d_in, const int* in_sizes, int n_in,
                              void* d_out, int out_size)
{
    const float* x    = (const float*)d_in[0];  // [256,1024,64]
    const float* kern = (const float*)d_in[1];  // [64,256]
    const float* rec  = (const float*)d_in[2];  // [64,256]
    const float* bias = (const float*)d_in[3];  // [256]
    const float* dw   = (const float*)d_in[4];  // [64,1]
    const float* db   = (const float*)d_in[5];  // [1]
    float* out = (float*)d_out;                 // [256,1024,1]

    lstm_xgemm<<<1024, 256>>>(x, kern, bias);
    lstm_recur<<<256, 128>>>(rec, dw, db, out);
}